// round 1
// baseline (speedup 1.0000x reference)
#include <cuda_runtime.h>

// RLGate: B=4, T=2048, D=1024, E=8, K=2
// Inputs (metadata order):
//   0: x               [B,T,D]   f32
//   1: expert_outputs  [E,B,T,D] f32
//   2: rewards         [B,T]     f32
//   3: W               [D,E]     f32
//   4: b               [E]       f32
//   5: baseline_value  []        f32
//   6: noise_u         [B,T,E]   f32
//   7: top_k           scalar    int32
// Output: final_output [B,T,D] f32 followed by aux_loss scalar (out_size = B*T*D + 1)

#define BB   4
#define TT   2048
#define DD   1024
#define EE   8
#define NTOK (BB * TT)      // 8192
#define EPSF 1e-9f

__global__ void rlgate_zero_aux(float* __restrict__ out) {
    out[(size_t)NTOK * DD] = 0.0f;
}

__global__ __launch_bounds__(256, 4) void rlgate_kernel(
    const float* __restrict__ x,
    const float* __restrict__ eo,
    const float* __restrict__ rewards,
    const float* __restrict__ W,
    const float* __restrict__ bias,
    const float* __restrict__ baseline,
    const float* __restrict__ noise_u,
    float* __restrict__ out)
{
    const int tok = blockIdx.x;           // 0..8191
    const int tid = threadIdx.x;          // 0..255, handles d = 4*tid .. 4*tid+3
    const int lane = tid & 31;
    const int warp = tid >> 5;

    // ---- 1) load x row (coalesced float4) and accumulate 8 dot partials ----
    const float4 xv = reinterpret_cast<const float4*>(x + (size_t)tok * DD)[tid];

    float acc[EE];
    #pragma unroll
    for (int e = 0; e < EE; e++) acc[e] = 0.0f;

    const float* wbase = W + (size_t)(4 * tid) * EE;   // 4 consecutive rows of W[D,E]
    const float xs[4] = {xv.x, xv.y, xv.z, xv.w};
    #pragma unroll
    for (int j = 0; j < 4; j++) {
        const float4 w0 = reinterpret_cast<const float4*>(wbase + j * EE)[0];
        const float4 w1 = reinterpret_cast<const float4*>(wbase + j * EE)[1];
        acc[0] = fmaf(xs[j], w0.x, acc[0]);
        acc[1] = fmaf(xs[j], w0.y, acc[1]);
        acc[2] = fmaf(xs[j], w0.z, acc[2]);
        acc[3] = fmaf(xs[j], w0.w, acc[3]);
        acc[4] = fmaf(xs[j], w1.x, acc[4]);
        acc[5] = fmaf(xs[j], w1.y, acc[5]);
        acc[6] = fmaf(xs[j], w1.z, acc[6]);
        acc[7] = fmaf(xs[j], w1.w, acc[7]);
    }

    // ---- 2) warp reduce, then cross-warp reduce in shared ----
    #pragma unroll
    for (int off = 16; off > 0; off >>= 1) {
        #pragma unroll
        for (int e = 0; e < EE; e++)
            acc[e] += __shfl_down_sync(0xFFFFFFFFu, acc[e], off);
    }

    __shared__ float sred[8][EE];
    __shared__ int   sidx[2];
    if (lane == 0) {
        #pragma unroll
        for (int e = 0; e < EE; e++) sred[warp][e] = acc[e];
    }
    __syncthreads();

    // ---- 3) softmax + log + gumbel + top-2 + aux (single thread; E=8) ----
    if (tid == 0) {
        float logits[EE];
        #pragma unroll
        for (int e = 0; e < EE; e++) {
            float s = 0.0f;
            #pragma unroll
            for (int w = 0; w < 8; w++) s += sred[w][e];
            logits[e] = s + bias[e];
        }
        float mx = logits[0];
        #pragma unroll
        for (int e = 1; e < EE; e++) mx = fmaxf(mx, logits[e]);
        float p[EE], sum = 0.0f;
        #pragma unroll
        for (int e = 0; e < EE; e++) { p[e] = __expf(logits[e] - mx); sum += p[e]; }
        const float inv = 1.0f / sum;

        float lp[EE], sc[EE];
        const float* nu = noise_u + (size_t)tok * EE;
        #pragma unroll
        for (int e = 0; e < EE; e++) {
            lp[e] = logf(p[e] * inv + EPSF);
            float u = nu[e] * (1.0f - 2e-7f) + 1e-7f;
            sc[e] = lp[e] - logf(-logf(u));   // log_prob + gumbel
        }
        // argmax twice, strict '>' keeps lowest index on ties (matches lax.top_k)
        int i0 = 0;
        #pragma unroll
        for (int e = 1; e < EE; e++) if (sc[e] > sc[i0]) i0 = e;
        int i1 = (i0 == 0) ? 1 : 0;
        #pragma unroll
        for (int e = 0; e < EE; e++) if (e != i0 && sc[e] > sc[i1]) i1 = e;

        sidx[0] = i0;
        sidx[1] = i1;

        const float adv = rewards[tok] - baseline[0];
        const float contrib = -(adv * (lp[i0] + lp[i1])) * (1.0f / (float)NTOK);
        atomicAdd(out + (size_t)NTOK * DD, contrib);
    }
    __syncthreads();

    // ---- 4) gather two expert rows, average, write out ----
    const int i0 = sidx[0];
    const int i1 = sidx[1];
    const size_t base = (size_t)tok * DD;
    const float4 a = reinterpret_cast<const float4*>(eo + (size_t)i0 * NTOK * DD + base)[tid];
    const float4 c = reinterpret_cast<const float4*>(eo + (size_t)i1 * NTOK * DD + base)[tid];
    float4 r;
    r.x = (a.x + c.x) * 0.5f;
    r.y = (a.y + c.y) * 0.5f;
    r.z = (a.z + c.z) * 0.5f;
    r.w = (a.w + c.w) * 0.5f;
    reinterpret_cast<float4*>(out + base)[tid] = r;
}

extern "C" void kernel_launch(void* const* d_in, const int* in_sizes, int n_in,
                              void* d_out, int out_size) {
    const float* x        = (const float*)d_in[0];
    const float* eo       = (const float*)d_in[1];
    const float* rewards  = (const float*)d_in[2];
    const float* W        = (const float*)d_in[3];
    const float* bias     = (const float*)d_in[4];
    const float* baseline = (const float*)d_in[5];
    const float* noise_u  = (const float*)d_in[6];
    float* out = (float*)d_out;

    rlgate_zero_aux<<<1, 1>>>(out);
    rlgate_kernel<<<NTOK, 256>>>(x, eo, rewards, W, bias, baseline, noise_u, out);
}

// round 2
// speedup vs baseline: 2.9342x; 2.9342x over previous
#include <cuda_runtime.h>

// RLGate: B=4, T=2048, D=1024, E=8, K=2
// Inputs: x[B,T,D] f32, expert_outputs[E,B,T,D] f32, rewards[B,T] f32,
//         W[D,E] f32, b[E] f32, baseline[] f32, noise_u[B,T,E] f32, top_k i32
// Output: final_output[B,T,D] f32 + aux_loss scalar at index B*T*D

#define BB      4
#define TT      2048
#define DD      1024
#define EE      8
#define NTOK    (BB * TT)          // 8192
#define TPB_TOK 16                  // tokens per CTA
#define NCTA    (NTOK / TPB_TOK)    // 512
#define EPSF    1e-9f

__global__ void rlgate_zero_aux(float* __restrict__ out) {
    out[(size_t)NTOK * DD] = 0.0f;
}

__global__ __launch_bounds__(256) void rlgate_kernel(
    const float* __restrict__ x,
    const float* __restrict__ eo,
    const float* __restrict__ rewards,
    const float* __restrict__ W,
    const float* __restrict__ bias,
    const float* __restrict__ baseline,
    const float* __restrict__ noise_u,
    float* __restrict__ out)
{
    const int tid  = threadIdx.x;
    const int lane = tid & 31;
    const int warp = tid >> 5;
    const int tokBase = blockIdx.x * TPB_TOK;

    __shared__ __align__(16) float Wt[EE][1032];        // transposed W, padded rows
    __shared__ float part[TPB_TOK][64];                 // per-warp expert partials
    __shared__ float logit_s[TPB_TOK][EE];
    __shared__ int   sidx_s[TPB_TOK][2];

    // ---- Phase 0: stage W -> smem transposed (coalesced gmem, ~2-way STS) ----
    const float4* W4 = reinterpret_cast<const float4*>(W);   // 2048 float4
    #pragma unroll
    for (int k = 0; k < 8; k++) {
        int idx = tid + 256 * k;          // float4 index
        float4 wv = W4[idx];
        int d  = idx >> 1;
        int e0 = (idx & 1) * 4;
        Wt[e0 + 0][d] = wv.x;
        Wt[e0 + 1][d] = wv.y;
        Wt[e0 + 2][d] = wv.z;
        Wt[e0 + 3][d] = wv.w;
    }
    __syncthreads();

    // hoist this thread's W slice (d = 4*tid..4*tid+3, all 8 experts) to regs.
    // LDS.128, lane-stride 16B -> conflict-free.
    float wr[EE][4];
    #pragma unroll
    for (int e = 0; e < EE; e++) {
        float4 t4 = *reinterpret_cast<const float4*>(&Wt[e][4 * tid]);
        wr[e][0] = t4.x; wr[e][1] = t4.y; wr[e][2] = t4.z; wr[e][3] = t4.w;
    }

    // ---- Phase 1: logits partials for all 16 tokens ----
    const float4* X4 = reinterpret_cast<const float4*>(x);
    #pragma unroll 2
    for (int t = 0; t < TPB_TOK; t++) {
        const int tok = tokBase + t;
        const float4 xv = X4[(size_t)tok * (DD / 4) + tid];

        float v[EE];
        #pragma unroll
        for (int e = 0; e < EE; e++) {
            v[e] = xv.x * wr[e][0];
            v[e] = fmaf(xv.y, wr[e][1], v[e]);
            v[e] = fmaf(xv.z, wr[e][2], v[e]);
            v[e] = fmaf(xv.w, wr[e][3], v[e]);
        }

        // 16-shuffle multi-value warp reduction (split after each round)
        #pragma unroll
        for (int e = 0; e < EE; e++) v[e] += __shfl_xor_sync(0xFFFFFFFFu, v[e], 16);
        if (lane & 16) { v[0] = v[4]; v[1] = v[5]; v[2] = v[6]; v[3] = v[7]; }
        #pragma unroll
        for (int i = 0; i < 4; i++)  v[i] += __shfl_xor_sync(0xFFFFFFFFu, v[i], 8);
        if (lane & 8)  { v[0] = v[2]; v[1] = v[3]; }
        #pragma unroll
        for (int i = 0; i < 2; i++)  v[i] += __shfl_xor_sync(0xFFFFFFFFu, v[i], 4);
        if (lane & 4)  { v[0] = v[1]; }
        v[0] += __shfl_xor_sync(0xFFFFFFFFu, v[0], 2);
        v[0] += __shfl_xor_sync(0xFFFFFFFFu, v[0], 1);
        // lane 4*e now holds the warp sum for expert e
        if ((lane & 3) == 0) part[t][warp * 8 + (lane >> 2)] = v[0];
    }
    __syncthreads();

    // ---- Phase 2a: cross-warp sum -> logits (128 threads) ----
    if (tid < TPB_TOK * EE) {
        const int t = tid >> 3, e = tid & 7;
        float s = bias[e];
        #pragma unroll
        for (int w = 0; w < 8; w++) s += part[t][w * 8 + e];
        logit_s[t][e] = s;
    }
    __syncthreads();

    // ---- Phase 2b: softmax + gumbel top-2 + aux (16 threads, parallel) ----
    float contrib = 0.0f;
    if (tid < TPB_TOK) {
        const int t = tid;
        const int tok = tokBase + t;
        float l[EE];
        #pragma unroll
        for (int e = 0; e < EE; e++) l[e] = logit_s[t][e];
        float mx = l[0];
        #pragma unroll
        for (int e = 1; e < EE; e++) mx = fmaxf(mx, l[e]);
        float p[EE], sum = 0.0f;
        #pragma unroll
        for (int e = 0; e < EE; e++) { p[e] = __expf(l[e] - mx); sum += p[e]; }
        const float inv = 1.0f / sum;

        float lp[EE], sc[EE];
        const float* nu = noise_u + (size_t)tok * EE;
        #pragma unroll
        for (int e = 0; e < EE; e++) {
            lp[e] = logf(p[e] * inv + EPSF);
            float u = nu[e] * (1.0f - 2e-7f) + 1e-7f;
            sc[e] = lp[e] - logf(-logf(u));       // log_prob + gumbel
        }
        int i0 = 0;
        #pragma unroll
        for (int e = 1; e < EE; e++) if (sc[e] > sc[i0]) i0 = e;
        int i1 = (i0 == 0) ? 1 : 0;
        #pragma unroll
        for (int e = 0; e < EE; e++) if (e != i0 && sc[e] > sc[i1]) i1 = e;

        sidx_s[t][0] = i0;
        sidx_s[t][1] = i1;

        const float adv = rewards[tok] - baseline[0];
        contrib = -(adv * (lp[i0] + lp[i1])) * (1.0f / (float)NTOK);
    }
    if (tid < 32) {
        #pragma unroll
        for (int off = 8; off > 0; off >>= 1)
            contrib += __shfl_down_sync(0xFFFFFFFFu, contrib, off);
        if (lane == 0) atomicAdd(out + (size_t)NTOK * DD, contrib);
    }
    __syncthreads();

    // ---- Phase 3: gather 2 expert rows per token, average, write ----
    const float4* EO4 = reinterpret_cast<const float4*>(eo);
    float4* OUT4 = reinterpret_cast<float4*>(out);
    #pragma unroll 2
    for (int t = 0; t < TPB_TOK; t++) {
        const int tok = tokBase + t;
        const int i0 = sidx_s[t][0];
        const int i1 = sidx_s[t][1];
        const size_t base4 = (size_t)tok * (DD / 4) + tid;
        const float4 a = EO4[(size_t)i0 * NTOK * (DD / 4) + base4];
        const float4 c = EO4[(size_t)i1 * NTOK * (DD / 4) + base4];
        float4 r;
        r.x = (a.x + c.x) * 0.5f;
        r.y = (a.y + c.y) * 0.5f;
        r.z = (a.z + c.z) * 0.5f;
        r.w = (a.w + c.w) * 0.5f;
        OUT4[base4] = r;
    }
}

extern "C" void kernel_launch(void* const* d_in, const int* in_sizes, int n_in,
                              void* d_out, int out_size) {
    const float* x        = (const float*)d_in[0];
    const float* eo       = (const float*)d_in[1];
    const float* rewards  = (const float*)d_in[2];
    const float* W        = (const float*)d_in[3];
    const float* bias     = (const float*)d_in[4];
    const float* baseline = (const float*)d_in[5];
    const float* noise_u  = (const float*)d_in[6];
    float* out = (float*)d_out;

    rlgate_zero_aux<<<1, 1>>>(out);
    rlgate_kernel<<<NCTA, 256>>>(x, eo, rewards, W, bias, baseline, noise_u, out);
}